// round 9
// baseline (speedup 1.0000x reference)
#include <cuda_runtime.h>

#define NUMLAB 670000
#define Bn 128
#define Cn 65536
#define Mn 16
#define Hn 512
#define Kn 200
#define KMn 3200        // Kn*Mn
#define SBn 16          // scan segments per row
#define SEGCAP 128      // survivor capacity per segment (expected ~25)
#define ROWCAP (SBn * SEGCAP)  // 2048
#define EPT 13          // expand entries per thread (13*256 >= 3200)

#define NBLK_COLLECT (SBn * Bn)          // 2048
#define NBLK_SELECT  (Bn)                // 128
#define NBLK_SCORE   (Bn * (KMn / 32))   // 12800 (32 cands per block)
#define NBLK_TOTAL   (NBLK_COLLECT + NBLK_SELECT + NBLK_SCORE)

// ---- scratch (no allocations allowed; zero-initialized statics) ----
__device__ int      g_scnt[Bn * SBn];
__device__ unsigned g_su[Bn * SBn * SEGCAP];
__device__ int      g_si[Bn * SBn * SEGCAP];
__device__ int      g_cands[Bn * KMn];
__device__ float    g_cscores[Bn * KMn];
__device__ int      g_segdone[Bn];    // collect -> select (counts to SBn, reset by select)
__device__ int      g_rowready[Bn];   // select -> score  (set 1, reset by last score block)
__device__ int      g_scoredone[Bn];  // score completion counter (reset by last)

struct SelSmem {
    unsigned bu[ROWCAP];
    int      bi[ROWCAP];
    int      segcnt[SBn];
    int      segoff[SBn + 1];
    int      tidx[Kn];
    float    tsc[Kn];
    int      wsum[8];
    int      total;
    unsigned red[256];
    unsigned prefix;
    int      kneed;
    int      cnt;
    int      bad;
};
struct ScoSmem { float sh[Hn]; };
struct ColSmem { unsigned u[SEGCAP]; int i[SEGCAP]; int cnt; };
union Smem { SelSmem sel; ScoSmem sco; ColSmem col; };

// monotone float->uint key: descending float == descending key
__device__ __forceinline__ unsigned fkey(float x) {
    unsigned u = __float_as_uint(x);
    return (u & 0x80000000u) ? ~u : (u | 0x80000000u);
}

// ============================================================
// Role 1: streaming collect (bid in [0, 2048)). 16 segs/row.
// ============================================================
__device__ void collect_role(Smem& sm, const float* __restrict__ logits, int bid) {
    const int row = bid >> 4;
    const int seg = bid & 15;
    const int n4  = Cn / 4 / SBn;                 // 1024 float4 per block
    const float4* rp4 = (const float4*)(logits + (size_t)row * Cn) + seg * n4;
    const int base = seg * n4 * 4;
    const int tid = threadIdx.x;

    if (tid == 0) sm.col.cnt = 0;
    __syncthreads();

    float4 a0 = rp4[tid];
    float4 a1 = rp4[tid + 256];
    float4 a2 = rp4[tid + 512];
    float4 a3 = rp4[tid + 768];

    float vals[16] = {a0.x,a0.y,a0.z,a0.w, a1.x,a1.y,a1.z,a1.w,
                      a2.x,a2.y,a2.z,a2.w, a3.x,a3.y,a3.z,a3.w};
    #pragma unroll
    for (int t = 0; t < 16; t++) {
        if (vals[t] > 2.5f) {
            int p = atomicAdd(&sm.col.cnt, 1);
            if (p < SEGCAP) {
                sm.col.u[p] = fkey(vals[t]);
                sm.col.i[p] = base + (t >> 2) * 1024 + tid * 4 + (t & 3);
            }
        }
    }
    __syncthreads();
    const int c  = sm.col.cnt;
    const int cc = min(c, SEGCAP);
    const size_t off = (size_t)(row * SBn + seg) * SEGCAP;
    if (tid < cc) {
        g_su[off + tid] = sm.col.u[tid];
        g_si[off + tid] = sm.col.i[tid];
    }
    if (tid == 0) g_scnt[row * SBn + seg] = c;
    __threadfence();
    __syncthreads();
    if (tid == 0) atomicAdd(&g_segdone[row], 1);
}

// ============================================================
// Role 2: per-row exact top-200 rank-select + cluster expand +
// stable pad-compaction (bid - 2048 = row). 256 threads.
// ============================================================
__device__ void select_role(Smem& sm, const float* __restrict__ logits,
                            const int* __restrict__ clusters,
                            float* __restrict__ out, int row) {
    const int tid = threadIdx.x;
    const int lane = tid & 31;
    const int wid  = tid >> 5;
    const float*  rp  = logits + (size_t)row * Cn;
    const float4* rp4 = (const float4*)rp;

    // wait for this row's 16 collect segments
    if (tid == 0) {
        volatile int* p = &g_segdone[row];
        while (*p != SBn) __nanosleep(1000);
    }
    __syncthreads();
    __threadfence();

    if (tid < SBn) sm.sel.segcnt[tid] = g_scnt[row * SBn + tid];
    __syncthreads();
    if (tid == 0) {
        int acc = 0, bad = 0;
        #pragma unroll
        for (int s = 0; s < SBn; s++) {
            sm.sel.segoff[s] = acc;
            int c = sm.sel.segcnt[s];
            if (c > SEGCAP) bad = 1;
            acc += min(c, SEGCAP);
        }
        sm.sel.segoff[SBn] = acc;
        if (acc < Kn) bad = 1;
        sm.sel.bad = bad;
    }
    __syncthreads();

    int m;
    if (!sm.sel.bad) {
        m = sm.sel.segoff[SBn];
        // coalesced gather: 16 threads per segment
        {
            const int s  = tid >> 4;            // 0..15
            const int lt = tid & 15;
            const int cnt = sm.sel.segoff[s + 1] - sm.sel.segoff[s];
            const size_t off = (size_t)(row * SBn + s) * SEGCAP;
            for (int i = lt; i < cnt; i += 16) {
                sm.sel.bu[sm.sel.segoff[s] + i] = g_su[off + i];
                sm.sel.bi[sm.sel.segoff[s] + i] = g_si[off + i];
            }
        }
        __syncthreads();
    } else {
        // ---- fallback: exact radix select of the Kn-th largest key ----
        if (tid == 0) { sm.sel.prefix = 0u; sm.sel.kneed = Kn; sm.sel.cnt = 0; }
        __syncthreads();
        for (int shift = 24; shift >= 0; shift -= 8) {
            if (tid < 256) sm.sel.red[tid] = 0u;
            __syncthreads();
            const unsigned pref = sm.sel.prefix;
            const unsigned mhi  = (shift == 24) ? 0u : (0xFFFFFFFFu << (shift + 8));
            for (int i = tid; i < Cn / 4; i += 256) {
                float4 v = rp4[i];
                float vals[4] = {v.x, v.y, v.z, v.w};
                #pragma unroll
                for (int t = 0; t < 4; t++) {
                    unsigned u = fkey(vals[t]);
                    if ((u & mhi) == pref) atomicAdd(&sm.sel.red[(u >> shift) & 255], 1u);
                }
            }
            __syncthreads();
            if (tid == 0) {
                int kneed = sm.sel.kneed;
                int cum = 0;
                int b = 255;
                for (; b > 0; b--) {
                    int c = (int)sm.sel.red[b];
                    if (cum + c >= kneed) break;
                    cum += c;
                }
                sm.sel.kneed  = kneed - cum;
                sm.sel.prefix = pref | ((unsigned)b << shift);
            }
            __syncthreads();
        }
        const unsigned T = sm.sel.prefix;
        for (int i = tid; i < Cn / 4; i += 256) {
            float4 v = rp4[i];
            float vals[4] = {v.x, v.y, v.z, v.w};
            #pragma unroll
            for (int t = 0; t < 4; t++) {
                unsigned u = fkey(vals[t]);
                if (u >= T) {
                    int p = atomicAdd(&sm.sel.cnt, 1);
                    if (p < ROWCAP) { sm.sel.bu[p] = u; sm.sel.bi[p] = i * 4 + t; }
                }
            }
        }
        __syncthreads();
        m = min(sm.sel.cnt, ROWCAP);
    }

    // ---- warp-cooperative exact rank-select (8 warps) ----
    for (int i = wid; i < m; i += 8) {
        const unsigned ui = sm.sel.bu[i];
        const int xi = sm.sel.bi[i];
        int r = 0;
        for (int j = lane; j < m; j += 32) {
            const unsigned uj = sm.sel.bu[j];
            r += (uj > ui || (uj == ui && sm.sel.bi[j] < xi)) ? 1 : 0;
        }
        #pragma unroll
        for (int off = 16; off; off >>= 1)
            r += __shfl_xor_sync(0xffffffffu, r, off);
        if (lane == 0 && r < Kn) {
            float v = rp[xi];
            sm.sel.tidx[r] = xi;
            sm.sel.tsc[r]  = 1.f / (1.f + __expf(-v));
        }
    }
    __syncthreads();

    // ---- expand clusters + stable pad-compaction (13 entries/thread) ----
    int cand[EPT];
    int nv = 0;
    const int e0 = tid * EPT;
    #pragma unroll
    for (int q = 0; q < EPT; q++) {
        const int e = e0 + q;
        int c = NUMLAB;
        if (e < KMn) {
            const int idx = min(max(sm.sel.tidx[e >> 4], 0), Cn - 1);
            c = clusters[(size_t)idx * Mn + (e & 15)];
        }
        cand[q] = c;
        if (e < KMn && c != NUMLAB) nv++;
    }
    // block scan of nv (warp shfl + 8-warp combine)
    int x = nv;
    #pragma unroll
    for (int off = 1; off < 32; off <<= 1) {
        int y = __shfl_up_sync(0xffffffffu, x, off);
        if (lane >= off) x += y;
    }
    if (lane == 31) sm.sel.wsum[wid] = x;
    __syncthreads();
    if (tid < 8) {
        int v = sm.sel.wsum[tid];
        int inc = v;
        #pragma unroll
        for (int off = 1; off < 8; off <<= 1) {
            int y = __shfl_up_sync(0x000000FFu, inc, off);
            if (tid >= off) inc += y;
        }
        sm.sel.wsum[tid] = inc - v;
        if (tid == 7) sm.sel.total = inc;
    }
    __syncthreads();
    const int total = sm.sel.total;
    int vb = sm.sel.wsum[wid] + x - nv;      // valids strictly before e0

    #pragma unroll
    for (int q = 0; q < EPT; q++) {
        const int e = e0 + q;
        if (e < KMn) {
            const int c = cand[q];
            const int valid = (c != NUMLAB);
            int pos;
            if (valid) { pos = vb; vb++; }
            else       { pos = total + e - vb; }
            g_cands[row * KMn + pos]   = c;
            g_cscores[row * KMn + pos] = valid ? sm.sel.tsc[e >> 4] : 0.f;
            out[(size_t)row * KMn + pos] = (float)c;
        }
    }

    __threadfence();
    __syncthreads();
    if (tid == 0) {
        g_segdone[row] = 0;                      // reset for next replay
        __threadfence();
        *(volatile int*)&g_rowready[row] = 1;    // publish
    }
}

// ============================================================
// Role 3: gather embeddings + dot with h_c, sigmoid, outputs.
// sb in [0, 12800): row = sb/100, 32 candidates per block.
// ============================================================
__device__ void score_role(Smem& sm, const float* __restrict__ h_c,
                           const float* __restrict__ table,
                           float* __restrict__ out, int sb) {
    const int row   = sb / 100;
    const int chunk = sb - row * 100;
    const int tid = threadIdx.x;

    for (int i = tid; i < Hn; i += 256) sm.sco.sh[i] = h_c[(size_t)row * Hn + i];

    if (tid == 0) {
        volatile int* p = &g_rowready[row];
        while (*p == 0) __nanosleep(1000);
    }
    __syncthreads();
    __threadfence();

    const int warp = tid >> 5;
    const int lane = tid & 31;
    const int c0 = chunk * 32 + warp * 4;
    const float4* hv = (const float4*)sm.sco.sh;

    #pragma unroll
    for (int t = 0; t < 4; t++) {
        const int c = c0 + t;
        int label = g_cands[row * KMn + c];
        label = min(max(label, 0), NUMLAB);
        const float4* er = (const float4*)(table + (size_t)label * Hn);
        float acc = 0.f;
        #pragma unroll
        for (int i = 0; i < 4; i++) {
            float4 e = er[lane + i * 32];
            float4 h = hv[lane + i * 32];
            acc += e.x * h.x;
            acc += e.y * h.y;
            acc += e.z * h.z;
            acc += e.w * h.w;
        }
        #pragma unroll
        for (int off = 16; off; off >>= 1)
            acc += __shfl_xor_sync(0xffffffffu, acc, off);
        if (lane == 0) {
            float s = (acc == 0.f) ? 0.f : (1.f / (1.f + __expf(-acc)));
            out[(size_t)Bn * KMn     + (size_t)row * KMn + c] = s;
            out[(size_t)Bn * KMn * 2 + (size_t)row * KMn + c] = s * g_cscores[row * KMn + c];
        }
    }

    __syncthreads();
    if (tid == 0) {
        int old = atomicAdd(&g_scoredone[row], 1);
        if (old == 99) {                 // last score block of this row: reset flags
            g_rowready[row]  = 0;
            g_scoredone[row] = 0;
        }
    }
}

// ============================================================
// Single fused kernel: role by blockIdx.
// ============================================================
__global__ void __launch_bounds__(256, 6) fused_kernel(const float* __restrict__ logits,
                                                       const int* __restrict__ clusters,
                                                       const float* __restrict__ h_c,
                                                       const float* __restrict__ table,
                                                       float* __restrict__ out) {
    __shared__ Smem sm;
    const int bid = blockIdx.x;
    if (bid < NBLK_COLLECT) {
        collect_role(sm, logits, bid);
    } else if (bid < NBLK_COLLECT + NBLK_SELECT) {
        select_role(sm, logits, clusters, out, bid - NBLK_COLLECT);
    } else {
        score_role(sm, h_c, table, out, bid - NBLK_COLLECT - NBLK_SELECT);
    }
}

extern "C" void kernel_launch(void* const* d_in, const int* in_sizes, int n_in,
                              void* d_out, int out_size) {
    // Bind inputs by element count (robust to metadata ordering):
    //   meta_logits  128*65536   = 8388608   f32
    //   h_c          128*512     = 65536     f32
    //   embed_table  670001*512  = 343040512 f32
    //   label_clusters 65536*16  = 1048576   i32 (jax x64 disabled -> int32)
    const float* meta = nullptr;
    const float* hc = nullptr;
    const float* table = nullptr;
    const int* clusters = nullptr;
    for (int i = 0; i < n_in; i++) {
        switch (in_sizes[i]) {
            case 8388608:   meta     = (const float*)d_in[i]; break;
            case 65536:     hc       = (const float*)d_in[i]; break;
            case 343040512: table    = (const float*)d_in[i]; break;
            case 1048576:   clusters = (const int*)d_in[i];   break;
            default: break;
        }
    }
    float* out = (float*)d_out; // 3 * 128 * 3200 f32: [cands | cand_scores | product]

    fused_kernel<<<NBLK_TOTAL, 256>>>(meta, clusters, hc, table, out);
}